// round 16
// baseline (speedup 1.0000x reference)
#include <cuda_runtime.h>
#include <cstdint>
#include <cstddef>

#define BB 8
#define LL 2048
#define HH 256
#define ROWS 64
#define JT 32
#define NTT (LL / JT)     // 64 tiles

typedef unsigned long long ull;

// -------- scratch (no allocations allowed: __device__ globals) --------
__device__ float g_base[LL];
__device__ float g_st[BB * LL];
__device__ float g_so[BB * LL];
__device__ float g_mult[BB * LL];
// pre-converted tf32 V, 2-k-block packed + bank-swizzled smem image:
// g_v4[((b*64+t)*8 + kb2*4 + tig)*256 + c] =
//   {V[k0][n], V[k0+4][n], V[k0+8][n], V[k0+12][n]},
//   k0 = t*32 + kb2*16 + tig, n = c ^ (tig*2)
__device__ float4 g_v4[BB * NTT * 8 * 256];    // 16.8 MB
// pre-converted W images (hi+lo planes packed in float4):
// g_w2[((which*8+kt)*16 + pair)*256 + c] = {Whi[n][k], Whi[n][k+4],
//                                           Wlo[n][k], Wlo[n][k+4]},
//   pair = kb*4+tig, k = kt*32+kb*8+tig, n = c ^ (tig*2)
__device__ float4 g_w2[2 * 8 * 16 * 256];      // 1 MB

// ---------------------------------------------------------------------
// helpers
// ---------------------------------------------------------------------
__device__ __forceinline__ unsigned cvt_tf32(float x) {
    unsigned r;
    asm("cvt.rna.tf32.f32 %0, %1;" : "=r"(r) : "f"(x));
    return r;
}
__device__ __forceinline__ void mma_tf32(float* c, unsigned a0, unsigned a1,
                                         unsigned a2, unsigned a3,
                                         unsigned b0, unsigned b1) {
    asm volatile(
        "mma.sync.aligned.m16n8k8.row.col.f32.tf32.tf32.f32 "
        "{%0,%1,%2,%3}, {%4,%5,%6,%7}, {%8,%9}, {%0,%1,%2,%3};"
        : "+f"(c[0]), "+f"(c[1]), "+f"(c[2]), "+f"(c[3])
        : "r"(a0), "r"(a1), "r"(a2), "r"(a3), "r"(b0), "r"(b1));
}
__device__ __forceinline__ void cp16(void* s, const void* g) {
    unsigned sa = (unsigned)__cvta_generic_to_shared(s);
    asm volatile("cp.async.cg.shared.global [%0], [%1], 16;\n" ::"r"(sa), "l"(g));
}
__device__ __forceinline__ float fast_tanh(float x) {
    float e = __expf(2.0f * x);
    return 1.0f - __fdividef(2.0f, e + 1.0f);
}

// ---------------------------------------------------------------------
// Kernel 0: base table + per-token column multiplier
// ---------------------------------------------------------------------
__global__ void k_base_mult(const int* __restrict__ pos) {
    int i = blockIdx.x * blockDim.x + threadIdx.x;
    if (i < LL) {
        g_base[i] = (i == 0) ? 0.5f : (1.0f / log2f(2.0f + (float)i));
    }
    if (i < BB * LL) {
        const unsigned long long mask =
            (1ULL << 19) | (1ULL << 20) | (1ULL << 21) |
            (1ULL << 33) | (1ULL << 34) | (1ULL << 35) |
            (1ULL << 41) | (1ULL << 42) | (1ULL << 43) |
            (1ULL << 44) | (1ULL << 45) | (1ULL << 46);
        int p = pos[i];
        bool op = (p >= 0) && (p < 64) && (((mask >> p) & 1ULL) != 0ULL);
        g_mult[i] = op ? 8.0f : 1.0f;
    }
}

// ---------------------------------------------------------------------
// Kernel 0b: V -> tf32, 2-k-block packed image (runs once)
// ---------------------------------------------------------------------
__global__ __launch_bounds__(256)
void k_v2(const float* __restrict__ V) {
    int bt = blockIdx.x;                 // b*64 + t
    int b = bt >> 6, t = bt & 63;
    const float* Vb = V + (size_t)b * LL * HH;
    float4* outp = g_v4 + (size_t)bt * 2048;
#pragma unroll
    for (int it = 0; it < 8; ++it) {
        int idx = it * 256 + threadIdx.x;    // 0..2047
        int p = idx >> 8, c = idx & 255;     // p = kb2*4 + tig
        int tig = p & 3, kb2 = p >> 2;
        int n = c ^ (tig * 2);
        int k0 = t * 32 + kb2 * 16 + tig;
        float4 o;
        o.x = __uint_as_float(cvt_tf32(Vb[(size_t)k0 * HH + n]));
        o.y = __uint_as_float(cvt_tf32(Vb[(size_t)(k0 + 4) * HH + n]));
        o.z = __uint_as_float(cvt_tf32(Vb[(size_t)(k0 + 8) * HH + n]));
        o.w = __uint_as_float(cvt_tf32(Vb[(size_t)(k0 + 12) * HH + n]));
        outp[idx] = o;
    }
}

// ---------------------------------------------------------------------
// Kernel 0c: W -> tf32 hi/lo pair image (runs once; tiny)
// ---------------------------------------------------------------------
__global__ __launch_bounds__(256)
void k_w2(const float* __restrict__ Wt, const float* __restrict__ Wo) {
    int which = blockIdx.x >> 3, kt = blockIdx.x & 7;
    const float* W = which ? Wo : Wt;
    float4* outp = g_w2 + (size_t)(which * 8 + kt) * 4096;
#pragma unroll
    for (int it = 0; it < 16; ++it) {
        int idx = it * 256 + threadIdx.x;    // 0..4095
        int p = idx >> 8, c = idx & 255;
        int tig = p & 3;
        int n = c ^ (tig * 2);
        int k = kt * 32 + (p >> 2) * 8 + tig;
        float w0 = W[n * 256 + k];
        float w1 = W[n * 256 + k + 4];
        float h0 = __uint_as_float(cvt_tf32(w0));
        float h1 = __uint_as_float(cvt_tf32(w1));
        float4 o;
        o.x = h0;
        o.y = h1;
        o.z = __uint_as_float(cvt_tf32(w0 - h0));
        o.w = __uint_as_float(cvt_tf32(w1 - h1));
        outp[idx] = o;
    }
}

// ---------------------------------------------------------------------
// Kernel 1: per-token transforms via tf32 mma, both transforms per CTA
// (sequential which-loop -> grid 256 = one wave).
// ---------------------------------------------------------------------
#define TR_SMEM (4096 * 16 + 64 * 36 * 4 + 256 * 4 + 256 * 4 + 128 * 4)

__global__ __launch_bounds__(256, 2)
void k_transform_mma(const float* __restrict__ text, const float* __restrict__ opinion,
                     const float* __restrict__ btp, const float* __restrict__ wa,
                     const float* __restrict__ ba) {
    extern __shared__ float sm[];
    float4* Wc     = (float4*)sm;            // 4096 float4 = 64 KB
    float*  Xs     = (float*)(Wc + 4096);    // 64*36 f
    float*  bias_s = Xs + 64 * 36;           // 256 f
    float*  wa_s   = bias_s + 256;           // 256 f
    float*  red    = wa_s + 256;             // 128 f

    int tid = threadIdx.x;
    int lane = tid & 31, wid = tid >> 5;
    int gid = lane >> 2, tig = lane & 3;
    int wm = wid & 3, wn = wid >> 2;
    int tok0 = blockIdx.x * 64;
    int r0 = wm * 16 + gid;

    for (int which = 0; which < 2; ++which) {
        __syncthreads();                     // prev epilogue fully done
        const float* X = which ? opinion : text;
        bias_s[tid] = which ? 0.0f : btp[tid];
        wa_s[tid] = (which ? (wa + HH) : wa)[tid];
        const float4* Wg = g_w2 + (size_t)which * 8 * 4096;

        float acc[16][4];
#pragma unroll
        for (int nt = 0; nt < 16; ++nt)
#pragma unroll
            for (int q = 0; q < 4; ++q) acc[nt][q] = 0.0f;

        for (int kt = 0; kt < 8; ++kt) {
            if (kt) __syncthreads();
#pragma unroll
            for (int r = 0; r < 16; ++r) {
                int idx = r * 256 + tid;
                cp16(Wc + idx, Wg + kt * 4096 + idx);
            }
#pragma unroll
            for (int r = 0; r < 2; ++r) {
                int ch = r * 256 + tid;
                int row = ch >> 3, c4 = (ch & 7) * 4;
                cp16(Xs + row * 36 + c4,
                     X + (size_t)(tok0 + row) * 256 + kt * 32 + c4);
            }
            asm volatile("cp.async.commit_group;\n");
            asm volatile("cp.async.wait_group 0;\n");
            __syncthreads();

#pragma unroll
            for (int kb = 0; kb < 4; ++kb) {
                int kk = kb * 8 + tig;
                unsigned a0 = cvt_tf32(Xs[r0 * 36 + kk]);
                unsigned a1 = cvt_tf32(Xs[(r0 + 8) * 36 + kk]);
                unsigned a2 = cvt_tf32(Xs[r0 * 36 + kk + 4]);
                unsigned a3 = cvt_tf32(Xs[(r0 + 8) * 36 + kk + 4]);

                const float4* Bq = Wc + (kb * 4 + tig) * 256 + wn * 128;
                int cx = gid ^ (tig * 2);
#pragma unroll
                for (int nt = 0; nt < 16; ++nt) {
                    float4 w4 = Bq[(nt * 8) ^ cx];
                    mma_tf32(acc[nt], a0, a1, a2, a3,
                             __float_as_uint(w4.x), __float_as_uint(w4.y));
                    mma_tf32(acc[nt], a0, a1, a2, a3,
                             __float_as_uint(w4.z), __float_as_uint(w4.w));
                }
            }
        }

        // ---- epilogue: tanh dot wa, reduce ----
        float p0 = 0.0f, p1 = 0.0f;
#pragma unroll
        for (int nt = 0; nt < 16; ++nt) {
            int col0 = wn * 128 + nt * 8 + 2 * tig;
            int col1 = col0 + 1;
            float b0 = bias_s[col0], b1 = bias_s[col1];
            float w0 = wa_s[col0], w1 = wa_s[col1];
            p0 += fast_tanh(acc[nt][0] + b0) * w0 + fast_tanh(acc[nt][1] + b1) * w1;
            p1 += fast_tanh(acc[nt][2] + b0) * w0 + fast_tanh(acc[nt][3] + b1) * w1;
        }
        p0 += __shfl_xor_sync(0xffffffffu, p0, 1);
        p0 += __shfl_xor_sync(0xffffffffu, p0, 2);
        p1 += __shfl_xor_sync(0xffffffffu, p1, 1);
        p1 += __shfl_xor_sync(0xffffffffu, p1, 2);
        __syncthreads();
        if (tig == 0) {
            red[wn * 64 + r0] = p0;
            red[wn * 64 + r0 + 8] = p1;
        }
        __syncthreads();
        if (tid < 64) {
            float e = which ? ba[0] : 0.0f;
            float* outp = which ? g_so : g_st;
            outp[tok0 + tid] = red[tid] + red[64 + tid] + e;
        }
    }
}

// ---------------------------------------------------------------------
// Kernel 2: attention. tf32 PV single mma; LDS.128 B frags (2 mmas per
// load via 2-k-block packed g_v4); one barrier per tile; 2 CTAs/SM.
// ---------------------------------------------------------------------
#define ATTN_SMEM (2 * 2048 * 16 + LL * 4 + LL * 4 + ROWS * 4)

__global__ __launch_bounds__(256, 2)
void k_attn(float* __restrict__ out) {
    extern __shared__ float sm[];
    float4* Vd    = (float4*)sm;             // 2 * 2048 float4 = 64 KB
    float*  base_s= (float*)(Vd + 2 * 2048); // 2048 f
    float*  sop   = base_s + LL;             // 2048 f
    float*  S_s   = sop + LL;                // 64 f

    int tid = threadIdx.x;
    int lane = tid & 31, wid = tid >> 5;
    int gid = lane >> 2, tig = lane & 3;
    int wm = wid & 3, wn = wid >> 2;
    int b = blockIdx.x >> 5;
    int row0 = (blockIdx.x & 31) * ROWS;

    const float4* V4g = g_v4 + (size_t)b * NTT * 2048;

    // prefetch tile 0 (2048 float4 = 32 KB)
#pragma unroll
    for (int r = 0; r < 8; ++r) {
        int chunk = r * 256 + tid;
        cp16(Vd + chunk, V4g + chunk);
    }
    asm volatile("cp.async.commit_group;\n");

    const float* sog = g_so + b * LL;
    const float* mug = g_mult + b * LL;
    for (int i = tid; i < LL; i += 256) {
        base_s[i] = g_base[i];
        unsigned u = __float_as_uint(sog[i]);
        u = (u & ~1u) | (mug[i] > 4.0f ? 1u : 0u);
        sop[i] = __uint_as_float(u);
    }

    int lr0 = wm * 16 + gid;
    int i0 = row0 + lr0, i1 = i0 + 8;
    float st0 = g_st[b * LL + i0];
    float st1 = g_st[b * LL + i1];

    float acc[16][4];
#pragma unroll
    for (int nt = 0; nt < 16; ++nt)
#pragma unroll
        for (int q = 0; q < 4; ++q) acc[nt][q] = 0.0f;
    float sum0 = 0.0f, sum1 = 0.0f;

    for (int t = 0; t < NTT; ++t) {
        asm volatile("cp.async.wait_group 0;\n");
        __syncthreads();   // fill(t) landed for all; compute(t-1) done for all

        if (t + 1 < NTT) {
            float4* dn = Vd + ((t + 1) & 1) * 2048;
            const float4* gs = V4g + (size_t)(t + 1) * 2048;
#pragma unroll
            for (int r = 0; r < 8; ++r) {
                int chunk = r * 256 + tid;
                cp16(dn + chunk, gs + chunk);
            }
            asm volatile("cp.async.commit_group;\n");
        }

        const float4* Vb4 = Vd + (t & 1) * 2048;
#pragma unroll
        for (int kb2 = 0; kb2 < 2; ++kb2) {
            int jb = t * JT + kb2 * 16;
            int jA0 = jb + tig, jA1 = jb + 8 + tig;
            float q0 = sop[jA0];
            float q1 = sop[jA0 + 4];
            float q2 = sop[jA1];
            float q3 = sop[jA1 + 4];
            float m0 = (__float_as_uint(q0) & 1u) ? 8.0f : 1.0f;
            float m1 = (__float_as_uint(q1) & 1u) ? 8.0f : 1.0f;
            float m2 = (__float_as_uint(q2) & 1u) ? 8.0f : 1.0f;
            float m3 = (__float_as_uint(q3) & 1u) ? 8.0f : 1.0f;
            int d00 = i0 - jA0;     d00 = (d00 < 0) ? -d00 : d00;
            int d10 = i1 - jA0;     d10 = (d10 < 0) ? -d10 : d10;
            int d01 = i0 - jA0 - 4; d01 = (d01 < 0) ? -d01 : d01;
            int d11 = i1 - jA0 - 4; d11 = (d11 < 0) ? -d11 : d11;
            int d02 = i0 - jA1;     d02 = (d02 < 0) ? -d02 : d02;
            int d12 = i1 - jA1;     d12 = (d12 < 0) ? -d12 : d12;
            int d03 = i0 - jA1 - 4; d03 = (d03 < 0) ? -d03 : d03;
            int d13 = i1 - jA1 - 4; d13 = (d13 < 0) ? -d13 : d13;
            float p00 = __expf(base_s[d00] * m0 * (st0 + q0));
            float p10 = __expf(base_s[d10] * m0 * (st1 + q0));
            float p01 = __expf(base_s[d01] * m1 * (st0 + q1));
            float p11 = __expf(base_s[d11] * m1 * (st1 + q1));
            float p02 = __expf(base_s[d02] * m2 * (st0 + q2));
            float p12 = __expf(base_s[d12] * m2 * (st1 + q2));
            float p03 = __expf(base_s[d03] * m3 * (st0 + q3));
            float p13 = __expf(base_s[d13] * m3 * (st1 + q3));
            sum0 += p00 + p01 + p02 + p03;
            sum1 += p10 + p11 + p12 + p13;
            unsigned a0 = cvt_tf32(p00), a1 = cvt_tf32(p10);
            unsigned a2 = cvt_tf32(p01), a3 = cvt_tf32(p11);
            unsigned a4 = cvt_tf32(p02), a5 = cvt_tf32(p12);
            unsigned a6 = cvt_tf32(p03), a7 = cvt_tf32(p13);

            const float4* Bp = Vb4 + (kb2 * 4 + tig) * 256 + wn * 128;
            int cx = gid ^ (tig * 2);
#pragma unroll
            for (int nt = 0; nt < 16; ++nt) {
                float4 bb = Bp[(nt * 8) ^ cx];
                mma_tf32(acc[nt], a0, a1, a2, a3,
                         __float_as_uint(bb.x), __float_as_uint(bb.y));
                mma_tf32(acc[nt], a4, a5, a6, a7,
                         __float_as_uint(bb.z), __float_as_uint(bb.w));
            }
        }
        // no bottom barrier: next iteration's top barrier orders
        // compute(t) before fill(t+2) reuses this buffer.
    }

    sum0 += __shfl_xor_sync(0xffffffffu, sum0, 1);
    sum0 += __shfl_xor_sync(0xffffffffu, sum0, 2);
    sum1 += __shfl_xor_sync(0xffffffffu, sum1, 1);
    sum1 += __shfl_xor_sync(0xffffffffu, sum1, 2);
    if (tig == 0 && wn == 0) {
        S_s[lr0] = sum0;
        S_s[lr0 + 8] = sum1;
    }
    __syncthreads();

    float inv0 = 1.0f / S_s[lr0];
    float inv1 = 1.0f / S_s[lr0 + 8];
    float* Ob = out + ((size_t)b * LL + row0) * HH;
#pragma unroll
    for (int nt = 0; nt < 16; ++nt) {
        int col = wn * 128 + nt * 8 + 2 * tig;
        *(float2*)(Ob + (size_t)lr0 * HH + col) =
            make_float2(acc[nt][0] * inv0, acc[nt][1] * inv0);
        *(float2*)(Ob + (size_t)(lr0 + 8) * HH + col) =
            make_float2(acc[nt][2] * inv1, acc[nt][3] * inv1);
    }
}

// ---------------------------------------------------------------------
extern "C" void kernel_launch(void* const* d_in, const int* in_sizes, int n_in,
                              void* d_out, int out_size) {
    const float* opinion = (const float*)d_in[0];
    const float* text    = (const float*)d_in[1];
    const int*   pos     = (const int*)d_in[2];
    const float* Wt      = (const float*)d_in[3];
    const float* bt      = (const float*)d_in[4];
    const float* Wo      = (const float*)d_in[5];
    const float* wa      = (const float*)d_in[6];
    const float* ba      = (const float*)d_in[7];
    float* out = (float*)d_out;

    cudaFuncSetAttribute(k_attn, cudaFuncAttributeMaxDynamicSharedMemorySize,
                         ATTN_SMEM);
    cudaFuncSetAttribute(k_transform_mma,
                         cudaFuncAttributeMaxDynamicSharedMemorySize, TR_SMEM);

    k_base_mult<<<(BB * LL + 255) / 256, 256>>>(pos);
    k_v2<<<BB * NTT, 256>>>(opinion);
    k_w2<<<16, 256>>>(Wt, Wo);
    k_transform_mma<<<BB * LL / 64, 256, TR_SMEM>>>(text, opinion, bt, wa, ba);
    k_attn<<<BB * (LL / ROWS), 256, ATTN_SMEM>>>(out);
}